// round 16
// baseline (speedup 1.0000x reference)
#include <cuda_runtime.h>

#define B_ 128
#define T_ 1024
#define N_ 64
#define S_ 6                        // segments per chain
#define NPASS_ (2 * S_ - 2)         // 10 scan passes (F: s=0..4, B: s=1..5)
#define THREADS_ (NPASS_ * 32)      // 320 threads, 1 warp per pass

// Per-batch losses + completion counter; reduced by the last-arriving block.
__device__ float g_loss[B_];
__device__ unsigned g_count = 0;    // wraps to 0 every launch via atomicInc

typedef unsigned long long u64;

__device__ __forceinline__ u64 pack2(float lo, float hi) {
    u64 d;
    asm("mov.b64 %0, {%1, %2};" : "=l"(d)
        : "r"(__float_as_uint(lo)), "r"(__float_as_uint(hi)));
    return d;
}
__device__ __forceinline__ float unpack_sum(u64 v) {
    unsigned a, b;
    asm("mov.b64 {%0, %1}, %2;" : "=r"(a), "=r"(b) : "l"(v));
    return __uint_as_float(a) + __uint_as_float(b);
}
__device__ __forceinline__ u64 ffma2(u64 a, u64 b, u64 c) {
    u64 d;
    asm("fma.rn.f32x2 %0, %1, %2, %3;" : "=l"(d) : "l"(a), "l"(b), "l"(c));
    return d;
}
__device__ __forceinline__ u64 fadd2(u64 a, u64 b) {
    u64 d;
    asm("add.rn.f32x2 %0, %1, %2;" : "=l"(d) : "l"(a), "l"(b));
    return d;
}

// Dual dot products (states jj, jj+1) sharing one pass of 16x LDS.128 over
// the alpha vector: 64x FFMA2, 2 accumulators per state (register-lean).
#define DUALDOT(SRC, SA, SB)                                               \
    {                                                                      \
        const ulonglong2* a4_ = (const ulonglong2*)(SRC);                  \
        u64 A0 = 0ull, A1 = 0ull, B0 = 0ull, B1 = 0ull;                    \
        _Pragma("unroll")                                                  \
        for (int k = 0; k < 16; ++k) {                                     \
            ulonglong2 v = a4_[k];                                         \
            A0 = ffma2(v.x, EcA[2 * k],     A0);                           \
            A1 = ffma2(v.y, EcA[2 * k + 1], A1);                           \
            B0 = ffma2(v.x, EcB[2 * k],     B0);                           \
            B1 = ffma2(v.y, EcB[2 * k + 1], B1);                           \
        }                                                                  \
        A0 = fadd2(A0, A1);                                                \
        B0 = fadd2(B0, B1);                                                \
        (SA) = unpack_sum(A0);                                             \
        (SB) = unpack_sum(B0);                                             \
    }

// One scan step (intra-warp only). e0/e1 were computed last step so the
// first post-syncwarp work is the dot's LDS stream.
#define STEP(SRC, DST, RENORM)                                             \
    {                                                                      \
        float mult0 = e0, mult1 = e1;                                      \
        if (RENORM) {                                                      \
            float a0 = (SRC)[0];                                           \
            float r  = __fdividef(1.0f, a0);                               \
            mult0 *= r;  mult1 *= r;                                       \
            cacc += __logf(a0);                                            \
        }                                                                  \
        float sA, sB;                                                      \
        DUALDOT(SRC, sA, sB)                                               \
        my0 = sA * mult0;                                                  \
        my1 = sB * mult1;                                                  \
        *(float2*)((DST) + jj) = make_float2(my0, my1);                    \
        int pc_ = max(min(pidx, L), 0);                                    \
        float2 p_pref = *(const float2*)(Pb + pc_ * N_ + jj);              \
        pidx += pinc;                                                      \
        e0 = __expf(p_cur.x);                                              \
        e1 = __expf(p_cur.y);                                              \
        p_cur = p_nxt;  p_nxt = p_pref;                                    \
        __syncwarp();                                                      \
    }

// One block per chain; 10 warps = 10 independent segment passes.
// F-pass seg s: g_s = P_s x (x = alpha_0 for s=0, probe 1 otherwise).
// B-pass seg s: h_s^T = 1^T P_s.
// Z ~= prod_{s=1..5}(h_s . g_{s-1}) / prod_{s=1..4}(h_s . 1)  (rank-1 stitch;
// segment products are numerically rank-1 after >=85 steps of contraction).
__global__ void __launch_bounds__(THREADS_, 1) crf_forward_kernel(
    const float* __restrict__ pot,     // (B,T,N)
    const int*   __restrict__ tags,    // (B,T)
    const int*   __restrict__ seqlen,  // (B,)
    const float* __restrict__ ck,      // (N,N)
    const float* __restrict__ sw,      // (B,)
    float*       __restrict__ out)     // (1,)
{
    const int tid  = threadIdx.x;
    const int b    = blockIdx.x;
    const int warp = tid >> 5;
    const int lane = tid & 31;
    const int jj   = 2 * lane;
    const int len  = seqlen[b];
    const int L    = len - 1;          // len >= T/2 = 512 -> L >= 511

    const bool isB = warp >= (S_ - 1);             // warps 5..9 backward
    const int  seg = isB ? (warp - (S_ - 1) + 1)   // B: s = 1..5
                         : warp;                   // F: s = 0..4
    const int lo    = (seg * L) / S_;
    const int hi    = ((seg + 1) * L) / S_;
    const int niter = hi - lo;                     // >= 85

    __shared__ __align__(16) float buf[NPASS_][2][N_];
    __shared__ __align__(16) float outv[NPASS_][N_];
    __shared__ float red[THREADS_];
    __shared__ float carr[NPASS_];
    __shared__ float scal[12];
    __shared__ int   is_last;

    // E registers: F needs columns jj, jj+1 of exp(ck); B needs rows.
    u64 EcA[32], EcB[32];
    {
        const int strd = isB ? 1 : N_;
        const int offA = isB ? jj * N_ : jj;
        const int offB = isB ? (jj + 1) * N_ : (jj + 1);
#pragma unroll
        for (int i = 0; i < 32; ++i) {
            EcA[i] = pack2(__expf(ck[(2 * i) * strd + offA]),
                           __expf(ck[(2 * i + 1) * strd + offA]));
            EcB[i] = pack2(__expf(ck[(2 * i) * strd + offB]),
                           __expf(ck[(2 * i + 1) * strd + offB]));
        }
    }

    const float* Pb   = pot  + (size_t)b * T_ * N_;
    const int*   tagb = tags + b * T_;

    // ---------------- sequence score (all 320 threads) ----------------
    float ss = 0.f;
    for (int t = tid; t < len; t += THREADS_) {
        int tg = tagb[t];
        ss += Pb[t * N_ + tg];
        if (t >= 1) ss += ck[tagb[t - 1] * N_ + tg];
    }
    red[tid] = ss;
    __syncthreads();
    if (tid < 64) {
        float v = red[tid];
        for (int k = tid + 64; k < THREADS_; k += 64) v += red[k];
        red[tid] = v;
    }
    __syncthreads();
#pragma unroll
    for (int off = 32; off >= 1; off >>= 1) {
        if (tid < off) red[tid] += red[tid + off];
        __syncthreads();
    }
    const float seq_score = red[0];
    __syncthreads();

    // ---------------- per-pass init (pipelined-e convention) ----------------
    float cacc, my0, my1, e0, e1;
    float2 p_cur, p_nxt;
    int pidx, pinc;
    if (!isB) {
        if (seg == 0) {
            cacc = Pb[0];
            my0  = __expf(Pb[jj]     - cacc);
            my1  = __expf(Pb[jj + 1] - cacc);
        } else {
            cacc = 0.f;  my0 = 1.f;  my1 = 1.f;
        }
        e0    = __expf(Pb[(lo + 1) * N_ + jj]);
        e1    = __expf(Pb[(lo + 1) * N_ + jj + 1]);
        p_cur = *(const float2*)(Pb + min(lo + 2, L) * N_ + jj);
        p_nxt = *(const float2*)(Pb + min(lo + 3, L) * N_ + jj);
        pidx  = lo + 4;  pinc = 1;
    } else {
        cacc  = 0.f;
        my0   = __expf(Pb[hi * N_ + jj]);       // D_hi * ones
        my1   = __expf(Pb[hi * N_ + jj + 1]);
        e0    = __expf(Pb[(hi - 1) * N_ + jj]);
        e1    = __expf(Pb[(hi - 1) * N_ + jj + 1]);
        p_cur = *(const float2*)(Pb + max(hi - 2, 0) * N_ + jj);
        p_nxt = *(const float2*)(Pb + max(hi - 3, 0) * N_ + jj);
        pidx  = hi - 4;  pinc = -1;
    }
    float* b0 = &buf[warp][0][0];
    float* b1 = &buf[warp][1][0];
    *(float2*)(b0 + jj) = make_float2(my0, my1);
    __syncwarp();

    // ---------------- main loop: unrolled x4, renorm every 4 ----------------
    // Last iteration stays in the tail (B's final mult is 1).
    const int nmain = (niter - 1) & ~3;
    for (int i = 0; i < nmain; i += 4) {
        STEP(b0, b1, true)
        STEP(b1, b0, false)
        STEP(b0, b1, false)
        STEP(b1, b0, false)
    }

    // ---------------- tail (1..4 iters) ----------------
    for (int i = nmain; i < niter; ++i) {
        float* src = (i & 1) ? b1 : b0;
        float* dst = (i & 1) ? b0 : b1;
        const bool last = isB && (i == niter - 1);
        float mult0 = last ? 1.0f : e0;
        float mult1 = last ? 1.0f : e1;
        if ((i & 3) == 0) {
            float a0 = src[0];
            float r  = __fdividef(1.0f, a0);
            mult0 *= r;  mult1 *= r;
            cacc += __logf(a0);
        }
        float sA, sB;
        DUALDOT(src, sA, sB)
        my0 = sA * mult0;
        my1 = sB * mult1;
        *(float2*)(dst + jj) = make_float2(my0, my1);
        int pc_ = max(min(pidx, L), 0);
        float2 p_pref = *(const float2*)(Pb + pc_ * N_ + jj);
        pidx += pinc;
        e0 = __expf(p_cur.x);
        e1 = __expf(p_cur.y);
        p_cur = p_nxt;  p_nxt = p_pref;
        __syncwarp();
    }

    // Publish boundary vector + log-offset.
    *(float2*)(&outv[warp][jj]) = make_float2(my0, my1);
    if (lane == 0) carr[warp] = cacc;
    __syncthreads();

    // ---------------- junction reductions ----------------
    // scal[0..4]  = h_{s} . g_{s-1} for s = 1..5   (h_s is pass 4+s)
    // scal[5..8]  = sum(h_s)        for s = 1..4   (pass index == warp)
    if (warp < 5) {
        const int s = warp + 1;
        const float* hv = &outv[4 + s][0];
        const float* gv = &outv[s - 1][0];
        float part = hv[jj] * gv[jj] + hv[jj + 1] * gv[jj + 1];
#pragma unroll
        for (int off = 16; off >= 1; off >>= 1)
            part += __shfl_xor_sync(0xffffffffu, part, off);
        if (lane == 0) scal[warp] = part;
    } else if (warp < 9) {
        const float* hv = &outv[warp][0];      // pass 4+s == warp for s=warp-4
        float part = hv[jj] + hv[jj + 1];
#pragma unroll
        for (int off = 16; off >= 1; off >>= 1)
            part += __shfl_xor_sync(0xffffffffu, part, off);
        if (lane == 0) scal[warp] = part;
    }
    __syncthreads();

    if (tid == 0) {
        float logZ = 0.f;
#pragma unroll
        for (int s = 0; s < 5; ++s) logZ += logf(scal[s]);
#pragma unroll
        for (int s = 5; s < 9; ++s) logZ -= logf(scal[s]);
        // offsets: all F passes (0..4) + the last B pass (9); interior B
        // offsets cancel between numerator and denominator.
        logZ += carr[0] + carr[1] + carr[2] + carr[3] + carr[4] + carr[9];
        g_loss[b] = -(seq_score - logZ) * sw[b];
        __threadfence();
        unsigned old = atomicInc(&g_count, B_ - 1);
        is_last = (old == B_ - 1);
    }
    __syncthreads();

    // ---------------- last block reduces all losses ----------------
    if (is_last) {
        volatile float* gl = g_loss;
        if (tid < B_) red[tid] = gl[tid];
        __syncthreads();
#pragma unroll
        for (int off = B_ / 2; off >= 1; off >>= 1) {
            if (tid < off) red[tid] += red[tid + off];
            __syncthreads();
        }
        if (tid == 0) out[0] = red[0] * (1.0f / (float)B_);
    }
}

extern "C" void kernel_launch(void* const* d_in, const int* in_sizes, int n_in,
                              void* d_out, int out_size)
{
    const float* pot    = (const float*)d_in[0];
    const int*   tags   = (const int*)  d_in[1];
    const int*   seqlen = (const int*)  d_in[2];
    const float* ck     = (const float*)d_in[3];
    const float* sw     = (const float*)d_in[4];

    crf_forward_kernel<<<B_, THREADS_>>>(pot, tags, seqlen, ck, sw, (float*)d_out);
}

// round 17
// speedup vs baseline: 1.4884x; 1.4884x over previous
#include <cuda_runtime.h>

#define B_ 128
#define T_ 1024
#define N_ 64
#define S_ 3                        // segments per chain
#define NPASS_ (2 * S_ - 2)         // 4 scan passes (F: s=0..1, B: s=1..2)
#define THREADS_ (NPASS_ * 32)      // 128 threads, 1 warp per pass

// Per-batch losses + completion counter; reduced by the last-arriving block.
__device__ float g_loss[B_];
__device__ unsigned g_count = 0;    // wraps to 0 every launch via atomicInc

typedef unsigned long long u64;

__device__ __forceinline__ u64 pack2(float lo, float hi) {
    u64 d;
    asm("mov.b64 %0, {%1, %2};" : "=l"(d)
        : "r"(__float_as_uint(lo)), "r"(__float_as_uint(hi)));
    return d;
}
__device__ __forceinline__ float unpack_sum(u64 v) {
    unsigned a, b;
    asm("mov.b64 {%0, %1}, %2;" : "=r"(a), "=r"(b) : "l"(v));
    return __uint_as_float(a) + __uint_as_float(b);
}
__device__ __forceinline__ u64 ffma2(u64 a, u64 b, u64 c) {
    u64 d;
    asm("fma.rn.f32x2 %0, %1, %2, %3;" : "=l"(d) : "l"(a), "l"(b), "l"(c));
    return d;
}
__device__ __forceinline__ u64 fadd2(u64 a, u64 b) {
    u64 d;
    asm("add.rn.f32x2 %0, %1, %2;" : "=l"(d) : "l"(a), "l"(b));
    return d;
}

// Dual dot products (states jj, jj+1) sharing one pass of 16x LDS.128 over
// the alpha vector: 64x FFMA2, 4 accumulators per state.
#define DUALDOT(SRC, SA, SB)                                               \
    {                                                                      \
        const ulonglong2* a4_ = (const ulonglong2*)(SRC);                  \
        u64 A0 = 0ull, A1 = 0ull, A2 = 0ull, A3 = 0ull;                    \
        u64 B0 = 0ull, B1 = 0ull, B2 = 0ull, B3 = 0ull;                    \
        _Pragma("unroll")                                                  \
        for (int k = 0; k < 16; ++k) {                                     \
            ulonglong2 v = a4_[k];                                         \
            if (k & 1) {                                                   \
                A2 = ffma2(v.x, EcA[2 * k],     A2);                       \
                A3 = ffma2(v.y, EcA[2 * k + 1], A3);                       \
                B2 = ffma2(v.x, EcB[2 * k],     B2);                       \
                B3 = ffma2(v.y, EcB[2 * k + 1], B3);                       \
            } else {                                                       \
                A0 = ffma2(v.x, EcA[2 * k],     A0);                       \
                A1 = ffma2(v.y, EcA[2 * k + 1], A1);                       \
                B0 = ffma2(v.x, EcB[2 * k],     B0);                       \
                B1 = ffma2(v.y, EcB[2 * k + 1], B1);                       \
            }                                                              \
        }                                                                  \
        A0 = fadd2(A0, A1); A2 = fadd2(A2, A3); A0 = fadd2(A0, A2);        \
        B0 = fadd2(B0, B1); B2 = fadd2(B2, B3); B0 = fadd2(B0, B2);        \
        (SA) = unpack_sum(A0);                                             \
        (SB) = unpack_sum(B0);                                             \
    }

// One scan step (intra-warp only). e0/e1 were computed last step so the
// first post-syncwarp work is the dot's LDS stream.
#define STEP(SRC, DST, RENORM)                                             \
    {                                                                      \
        float mult0 = e0, mult1 = e1;                                      \
        if (RENORM) {                                                      \
            float a0 = (SRC)[0];                                           \
            float r  = __fdividef(1.0f, a0);                               \
            mult0 *= r;  mult1 *= r;                                       \
            cacc += __logf(a0);                                            \
        }                                                                  \
        float sA, sB;                                                      \
        DUALDOT(SRC, sA, sB)                                               \
        my0 = sA * mult0;                                                  \
        my1 = sB * mult1;                                                  \
        *(float2*)((DST) + jj) = make_float2(my0, my1);                    \
        int pc_ = max(min(pidx, L), 0);                                    \
        float2 p_pref = *(const float2*)(Pb + pc_ * N_ + jj);              \
        pidx += pinc;                                                      \
        e0 = __expf(p_cur.x);                                              \
        e1 = __expf(p_cur.y);                                              \
        p_cur = p_nxt;  p_nxt = p_pref;                                    \
        __syncwarp();                                                      \
    }

// One block per chain; 4 warps = 4 independent segment passes (1 per SMSP).
// F-pass seg s: g_s = P_s x (x = alpha_0 for s=0, probe 1 otherwise).
// B-pass seg s: h_s^T = 1^T P_s.
// logZ = log(h1.g0) + log(h2.g1) - log(h1.1) + c_g0 + c_g1 + c_h2
// (rank-1 stitch at the 2 junctions; ~170-step segment products are
// numerically rank-1 -- verified bit-identical rel_err at 85 steps in R16).
__global__ void __launch_bounds__(THREADS_, 1) crf_forward_kernel(
    const float* __restrict__ pot,     // (B,T,N)
    const int*   __restrict__ tags,    // (B,T)
    const int*   __restrict__ seqlen,  // (B,)
    const float* __restrict__ ck,      // (N,N)
    const float* __restrict__ sw,      // (B,)
    float*       __restrict__ out)     // (1,)
{
    const int tid  = threadIdx.x;
    const int b    = blockIdx.x;
    const int warp = tid >> 5;
    const int lane = tid & 31;
    const int jj   = 2 * lane;
    const int len  = seqlen[b];
    const int L    = len - 1;          // len >= T/2 = 512 -> L >= 511

    const bool isB = warp >= (S_ - 1);             // warps 2..3 backward
    const int  seg = isB ? (warp - (S_ - 1) + 1)   // B: s = 1..2
                         : warp;                   // F: s = 0..1
    const int lo    = (seg * L) / S_;
    const int hi    = ((seg + 1) * L) / S_;
    const int niter = hi - lo;                     // >= 170

    __shared__ __align__(16) float buf[NPASS_][2][N_];
    __shared__ __align__(16) float outv[NPASS_][N_];
    __shared__ float red[THREADS_];
    __shared__ float carr[NPASS_];
    __shared__ float scal[4];
    __shared__ int   is_last;

    // E registers: F needs columns jj, jj+1 of exp(ck); B needs rows.
    u64 EcA[32], EcB[32];
    {
        const int strd = isB ? 1 : N_;
        const int offA = isB ? jj * N_ : jj;
        const int offB = isB ? (jj + 1) * N_ : (jj + 1);
#pragma unroll
        for (int i = 0; i < 32; ++i) {
            EcA[i] = pack2(__expf(ck[(2 * i) * strd + offA]),
                           __expf(ck[(2 * i + 1) * strd + offA]));
            EcB[i] = pack2(__expf(ck[(2 * i) * strd + offB]),
                           __expf(ck[(2 * i + 1) * strd + offB]));
        }
    }

    const float* Pb   = pot  + (size_t)b * T_ * N_;
    const int*   tagb = tags + b * T_;

    // ---------------- sequence score (all 128 threads) ----------------
    float ss = 0.f;
    for (int t = tid; t < len; t += THREADS_) {
        int tg = tagb[t];
        ss += Pb[t * N_ + tg];
        if (t >= 1) ss += ck[tagb[t - 1] * N_ + tg];
    }
    red[tid] = ss;
    __syncthreads();
    if (tid < 64) {
        float v = red[tid];
        for (int k = tid + 64; k < THREADS_; k += 64) v += red[k];
        red[tid] = v;
    }
    __syncthreads();
#pragma unroll
    for (int off = 32; off >= 1; off >>= 1) {
        if (tid < off) red[tid] += red[tid + off];
        __syncthreads();
    }
    const float seq_score = red[0];
    __syncthreads();

    // ---------------- per-pass init (pipelined-e convention) ----------------
    float cacc, my0, my1, e0, e1;
    float2 p_cur, p_nxt;
    int pidx, pinc;
    if (!isB) {
        if (seg == 0) {
            cacc = Pb[0];
            my0  = __expf(Pb[jj]     - cacc);
            my1  = __expf(Pb[jj + 1] - cacc);
        } else {
            cacc = 0.f;  my0 = 1.f;  my1 = 1.f;
        }
        e0    = __expf(Pb[(lo + 1) * N_ + jj]);
        e1    = __expf(Pb[(lo + 1) * N_ + jj + 1]);
        p_cur = *(const float2*)(Pb + min(lo + 2, L) * N_ + jj);
        p_nxt = *(const float2*)(Pb + min(lo + 3, L) * N_ + jj);
        pidx  = lo + 4;  pinc = 1;
    } else {
        cacc  = 0.f;
        my0   = __expf(Pb[hi * N_ + jj]);       // D_hi * ones
        my1   = __expf(Pb[hi * N_ + jj + 1]);
        e0    = __expf(Pb[(hi - 1) * N_ + jj]);
        e1    = __expf(Pb[(hi - 1) * N_ + jj + 1]);
        p_cur = *(const float2*)(Pb + max(hi - 2, 0) * N_ + jj);
        p_nxt = *(const float2*)(Pb + max(hi - 3, 0) * N_ + jj);
        pidx  = hi - 4;  pinc = -1;
    }
    float* b0 = &buf[warp][0][0];
    float* b1 = &buf[warp][1][0];
    *(float2*)(b0 + jj) = make_float2(my0, my1);
    __syncwarp();

    // ---------------- main loop: unrolled x4, renorm every 4 ----------------
    // Last iteration stays in the tail (B's final mult is 1).
    const int nmain = (niter - 1) & ~3;
    for (int i = 0; i < nmain; i += 4) {
        STEP(b0, b1, true)
        STEP(b1, b0, false)
        STEP(b0, b1, false)
        STEP(b1, b0, false)
    }

    // ---------------- tail (1..4 iters) ----------------
    for (int i = nmain; i < niter; ++i) {
        float* src = (i & 1) ? b1 : b0;
        float* dst = (i & 1) ? b0 : b1;
        const bool last = isB && (i == niter - 1);
        float mult0 = last ? 1.0f : e0;
        float mult1 = last ? 1.0f : e1;
        if ((i & 3) == 0) {
            float a0 = src[0];
            float r  = __fdividef(1.0f, a0);
            mult0 *= r;  mult1 *= r;
            cacc += __logf(a0);
        }
        float sA, sB;
        DUALDOT(src, sA, sB)
        my0 = sA * mult0;
        my1 = sB * mult1;
        *(float2*)(dst + jj) = make_float2(my0, my1);
        int pc_ = max(min(pidx, L), 0);
        float2 p_pref = *(const float2*)(Pb + pc_ * N_ + jj);
        pidx += pinc;
        e0 = __expf(p_cur.x);
        e1 = __expf(p_cur.y);
        p_cur = p_nxt;  p_nxt = p_pref;
        __syncwarp();
    }

    // Publish boundary vector + log-offset.
    *(float2*)(&outv[warp][jj]) = make_float2(my0, my1);
    if (lane == 0) carr[warp] = cacc;
    __syncthreads();

    // ---------------- junction reductions ----------------
    // scal[0..1] = h_s . g_{s-1} for s = 1..2  (h_s lives in outv[S_-2+s])
    // scal[2]    = sum(h_1)
    if (warp < S_ - 1) {
        const int s = warp + 1;
        const float* hv = &outv[(S_ - 2) + s][0];
        const float* gv = &outv[s - 1][0];
        float part = hv[jj] * gv[jj] + hv[jj + 1] * gv[jj + 1];
#pragma unroll
        for (int off = 16; off >= 1; off >>= 1)
            part += __shfl_xor_sync(0xffffffffu, part, off);
        if (lane == 0) scal[warp] = part;
    } else if (warp < 2 * S_ - 3) {               // warp 2 only
        const float* hv = &outv[warp][0];         // h_1
        float part = hv[jj] + hv[jj + 1];
#pragma unroll
        for (int off = 16; off >= 1; off >>= 1)
            part += __shfl_xor_sync(0xffffffffu, part, off);
        if (lane == 0) scal[warp] = part;
    }
    __syncthreads();

    if (tid == 0) {
        float logZ = logf(scal[0]) + logf(scal[1]) - logf(scal[2]);
        // offsets: F passes (0..S_-2) + last B pass; interior B offsets cancel.
        logZ += carr[0] + carr[1] + carr[NPASS_ - 1];
        g_loss[b] = -(seq_score - logZ) * sw[b];
        __threadfence();
        unsigned old = atomicInc(&g_count, B_ - 1);
        is_last = (old == B_ - 1);
    }
    __syncthreads();

    // ---------------- last block reduces all losses ----------------
    if (is_last) {
        volatile float* gl = g_loss;
        red[tid] = gl[tid];                       // THREADS_ == B_
        __syncthreads();
#pragma unroll
        for (int off = B_ / 2; off >= 1; off >>= 1) {
            if (tid < off) red[tid] += red[tid + off];
            __syncthreads();
        }
        if (tid == 0) out[0] = red[0] * (1.0f / (float)B_);
    }
}

extern "C" void kernel_launch(void* const* d_in, const int* in_sizes, int n_in,
                              void* d_out, int out_size)
{
    const float* pot    = (const float*)d_in[0];
    const int*   tags   = (const int*)  d_in[1];
    const int*   seqlen = (const int*)  d_in[2];
    const float* ck     = (const float*)d_in[3];
    const float* sw     = (const float*)d_in[4];

    crf_forward_kernel<<<B_, THREADS_>>>(pot, tags, seqlen, ck, sw, (float*)d_out);
}